// round 17
// baseline (speedup 1.0000x reference)
#include <cuda_runtime.h>

// Pixel-wise diagonal RNN:
//   h_t = leaky_relu(W_ih * x_t + W_hh * h_{t-1} + b_hh), h_0 = 0
// Streaming-bound; converged configuration (best ncu time of all rounds:
// 128.5us, DRAM 80.1% = practical HBM R/W-mix ceiling).
//  - 256-bit ld/st.global.v8.f32 (.cs streaming): one LDG.256 + one STG.256
//    per thread per timestep, fully-coalesced 1024B warp requests
//  - 512 CTAs = single perfectly-balanced wave (592 slots); each CTA runs
//    two chunks sequentially, outer loop not unrolled (reg blowup, R6)
//  - h carried in registers; compiler unroll-5 batches loads within the
//    register budget
// Probes that REGRESSED (do not revisit): explicit reg batching (R6),
// cp.async smem pipeline (R11), forced occupancy (R13), split-pair sector
// layout (R14).

#ifndef NEG_SLOPE
#define NEG_SLOPE 0.01f
#endif

struct __align__(32) f8 { float4 a, b; };

__device__ __forceinline__ f8 ldg256_cs(const f8* p) {
    f8 r;
    asm volatile("ld.global.cs.v8.f32 {%0,%1,%2,%3,%4,%5,%6,%7}, [%8];"
                 : "=f"(r.a.x), "=f"(r.a.y), "=f"(r.a.z), "=f"(r.a.w),
                   "=f"(r.b.x), "=f"(r.b.y), "=f"(r.b.z), "=f"(r.b.w)
                 : "l"(p));
    return r;
}

__device__ __forceinline__ void stg256_cs(f8* p, const f8& v) {
    asm volatile("st.global.cs.v8.f32 [%0], {%1,%2,%3,%4,%5,%6,%7,%8};"
                 :: "l"(p),
                    "f"(v.a.x), "f"(v.a.y), "f"(v.a.z), "f"(v.a.w),
                    "f"(v.b.x), "f"(v.b.y), "f"(v.b.z), "f"(v.b.w)
                 : "memory");
}

__global__ __launch_bounds__(256) void pixelwise_rnn_kernel(
    const f8* __restrict__ x,     // (T, P/8)
    const f8* __restrict__ w_ih,  // (P/8)
    const f8* __restrict__ w_hh,  // (P/8)
    const f8* __restrict__ b_hh,  // (P/8)
    f8* __restrict__ out,         // (T, P/8)
    int P8, int T, int nblocks)
{
    #pragma unroll 1
    for (int c = 0; c < 2; ++c) {
        int p = (blockIdx.x + c * nblocks) * blockDim.x + threadIdx.x;

        const f8 wi = w_ih[p];
        const f8 wh = w_hh[p];
        const f8 b  = b_hh[p];

        f8 h;
        h.a = make_float4(0.f, 0.f, 0.f, 0.f);
        h.b = make_float4(0.f, 0.f, 0.f, 0.f);

        const f8* xp = x + p;
        f8* op = out + p;

        #pragma unroll 5
        for (int t = 0; t < T; ++t) {
            size_t off = (size_t)t * P8;
            f8 xv = ldg256_cs(xp + off);

            float4 v0, v1;
            v0.x = fmaf(wi.a.x, xv.a.x, fmaf(wh.a.x, h.a.x, b.a.x));
            v0.y = fmaf(wi.a.y, xv.a.y, fmaf(wh.a.y, h.a.y, b.a.y));
            v0.z = fmaf(wi.a.z, xv.a.z, fmaf(wh.a.z, h.a.z, b.a.z));
            v0.w = fmaf(wi.a.w, xv.a.w, fmaf(wh.a.w, h.a.w, b.a.w));
            v1.x = fmaf(wi.b.x, xv.b.x, fmaf(wh.b.x, h.b.x, b.b.x));
            v1.y = fmaf(wi.b.y, xv.b.y, fmaf(wh.b.y, h.b.y, b.b.y));
            v1.z = fmaf(wi.b.z, xv.b.z, fmaf(wh.b.z, h.b.z, b.b.z));
            v1.w = fmaf(wi.b.w, xv.b.w, fmaf(wh.b.w, h.b.w, b.b.w));

            // leaky_relu with slope in (0,1): max(v, slope*v)
            h.a.x = fmaxf(v0.x, NEG_SLOPE * v0.x);
            h.a.y = fmaxf(v0.y, NEG_SLOPE * v0.y);
            h.a.z = fmaxf(v0.z, NEG_SLOPE * v0.z);
            h.a.w = fmaxf(v0.w, NEG_SLOPE * v0.w);
            h.b.x = fmaxf(v1.x, NEG_SLOPE * v1.x);
            h.b.y = fmaxf(v1.y, NEG_SLOPE * v1.y);
            h.b.z = fmaxf(v1.z, NEG_SLOPE * v1.z);
            h.b.w = fmaxf(v1.w, NEG_SLOPE * v1.w);

            stg256_cs(op + off, h);
        }
    }
}

extern "C" void kernel_launch(void* const* d_in, const int* in_sizes, int n_in,
                              void* d_out, int out_size)
{
    const float* x    = (const float*)d_in[0];  // (B=1, T, Z, H, W)
    const float* w_ih = (const float*)d_in[1];  // (Z, H, W)
    const float* w_hh = (const float*)d_in[2];
    const float* b_hh = (const float*)d_in[3];
    float* out = (float*)d_out;

    int P = in_sizes[1];            // Z*H*W = 2097152
    int T = in_sizes[0] / P;        // 50
    int P8 = P / 8;                 // 262144

    int threads = 256;
    int nblocks = P8 / threads / 2; // 512 CTAs, 2 chunks each, single wave
    pixelwise_rnn_kernel<<<nblocks, threads>>>(
        (const f8*)x, (const f8*)w_ih, (const f8*)w_hh,
        (const f8*)b_hh, (f8*)out, P8, T, nblocks);
}